// round 3
// baseline (speedup 1.0000x reference)
#include <cuda_runtime.h>

#define NBITS     20
#define NSTATES   (1u << NBITS)     // 2^20
#define QUARTER_N 262144.0f         // N/4
#define HALF_N    524288.0f         // N/2

// Single-block kernel. The buggy diag-gate cascade collapses the state to
// exactly zero at the 3rd Hadamard (fp32-exact: v0' = c*s, v1' = -c*s are
// exact negatives, so the next cross-qubit sum (N/4)(v0+v1) == 0). Hence
// probs == 0 and out = relu(b1)@W2 + b2. The W1 fallback is kept for
// mathematical faithfulness but never executes.
//
// Perf structure: all DRAM traffic (W2 -> SMEM via float4, b1, b2) is issued
// up front with full MLP and overlaps thread 0's scalar cascade; the matvec
// epilogue then runs entirely out of SMEM.
__global__ void qecm_kernel(const float* __restrict__ theta,  // [20,4]
                            const float* __restrict__ W1,     // [2^20,128]
                            const float* __restrict__ b1,     // [128]
                            const float* __restrict__ W2,     // [128,20]
                            const float* __restrict__ b2,     // [20]
                            float* __restrict__ out) {        // [1,20]
    __shared__ float    sh_W2[128 * NBITS];       // 10 KB
    __shared__ float    h[128];
    __shared__ float    sh_p0, sh_p1;
    __shared__ unsigned sh_mask;
    __shared__ int      sh_fast;
    const int tid = threadIdx.x;

    // ---- issue all global loads first (one DRAM round-trip, high MLP) ----
    const float4* W2v = (const float4*)W2;        // 2560 floats = 640 float4
    float4 w2r[5];
    #pragma unroll
    for (int i = 0; i < 5; i++) w2r[i] = W2v[tid + 128 * i];
    float b1v = b1[tid];
    float b2v = (tid < NBITS) ? b2[tid] : 0.0f;

    // ---- thread 0: scalar replay of the collapsed cascade (no memory) ----
    if (tid == 0) {
        const float c = 0.70710678118654752440f;  // 1/sqrt(2) in fp32
        float v0 = c, v1 = 0.0f;                  // H on q=0 applied to |0>
        int key = 0;
        for (int q = 1; q < NBITS; q++) {         // remaining Hadamards
            float s = QUARTER_N * (v0 + v1);      // cross-qubit: s0 == s1
            v0 =  c * s;
            v1 = -c * s;
            key = q;
            if (v0 == 0.0f && v1 == 0.0f) break;  // exact zero at q==2
        }
        if (v0 != 0.0f || v1 != 0.0f) {           // RX layers (zero-skipped)
            for (int k = 0; k < NBITS * 4; k++) {
                int q = k >> 2;
                float d = cosf(0.5f * theta[k]);
                float s0, s1;
                if (q == key) { s0 = HALF_N * v0;  s1 = HALF_N * v1; }
                else          { float s = QUARTER_N * (v0 + v1); s0 = s; s1 = s; }
                v0 = d * s0;  v1 = d * s1;  key = q;
                if (v0 == 0.0f && v1 == 0.0f) break;
            }
        }
        sh_p0   = v0 * v0;                        // state is real: |amp|^2
        sh_p1   = v1 * v1;
        sh_fast = (v0 == 0.0f) && (v1 == 0.0f);

        // CNOT ladder as GF(2)-linear map: bit_key(sigma(i)) = parity(i & m)
        unsigned L[NBITS];
        for (int b = 0; b < NBITS; b++) L[b] = 1u << b;
        for (int cc = NBITS - 2; cc >= 0; cc--)
            for (int tt = NBITS - 1; tt > cc; tt--)
                L[tt] ^= L[cc];
        sh_mask = L[NBITS - 1];
    }

    // ---- park W2 in shared (stores complete when loads land) ----
    #pragma unroll
    for (int i = 0; i < 5; i++)
        ((float4*)sh_W2)[tid + 128 * i] = w2r[i];
    __syncthreads();

    const float p0 = sh_p0, p1 = sh_p1;
    float S0 = 0.0f, S1 = 0.0f;

    if (!sh_fast) {
        // Never-taken fallback: probs is two-valued, so
        // probs@W1 = p0*S0 + p1*S1 with S_b[k] = sum over rows i with
        // parity(i & mask)==b of W1[i][k].
        const unsigned m = sh_mask;
        for (unsigned r = 0; r < NSTATES; r++) {
            float w = W1[(size_t)r * 128u + (unsigned)tid];
            if (__popc(r & m) & 1) S1 += w; else S0 += w;
        }
    }

    {   // h = relu(probs @ W1 + b1)  (== relu(b1) on the fast path)
        float z = fmaf(p0, S0, fmaf(p1, S1, b1v));
        h[tid] = z > 0.0f ? z : 0.0f;
    }
    __syncthreads();

    if (tid < NBITS) {                            // out = h @ W2 + b2 (SMEM)
        float acc = b2v;
        #pragma unroll
        for (int kk = 0; kk < 128; kk++)
            acc = fmaf(h[kk], sh_W2[kk * NBITS + tid], acc);
        out[tid] = acc;
    }
}

extern "C" void kernel_launch(void* const* d_in, const int* in_sizes, int n_in,
                              void* d_out, int out_size) {
    // input order: x [1,4] (unused), theta [20,4], W1 [2^20,128],
    //              b1 [128], W2 [128,20], b2 [20]; output float32 [1,20]
    (void)in_sizes; (void)n_in; (void)out_size;
    const float* theta = (const float*)d_in[1];
    const float* W1    = (const float*)d_in[2];
    const float* b1    = (const float*)d_in[3];
    const float* W2    = (const float*)d_in[4];
    const float* b2    = (const float*)d_in[5];
    qecm_kernel<<<1, 128>>>(theta, W1, b1, W2, b2, (float*)d_out);
}